// round 2
// baseline (speedup 1.0000x reference)
#include <cuda_runtime.h>

#define EMB   1024
#define NH    16
#define HD    64
#define SEQ   2048
#define BATCH 2
#define MTOT  (BATCH*SEQ)      // 4096
#define NQKV  (3*EMB)          // 3072

// Scratch (device globals: no allocation allowed in kernel_launch)
__device__ float g_q[BATCH*NH*SEQ*HD];
__device__ float g_k[BATCH*NH*SEQ*HD];
__device__ float g_v[BATCH*NH*SEQ*HD];
__device__ float g_attn[MTOT*EMB];

// ---------------------------------------------------------------------------
// Kernel 1: QKV = X @ Wqkv, fused RoPE on q/k, scatter to [B,H,T,D]
// 128x128 tile, K-step 8, 256 threads, 8x8 microtile.
// ---------------------------------------------------------------------------
__global__ __launch_bounds__(256)
void qkv_rope_kernel(const float* __restrict__ X, const float* __restrict__ W,
                     const float* __restrict__ cp, const float* __restrict__ snp)
{
    __shared__ float As[8][128];
    __shared__ float Bs[8][128];
    const int tid = threadIdx.x;
    const int tx = tid & 15, ty = tid >> 4;
    const int m0 = blockIdx.y * 128;
    const int n0 = blockIdx.x * 128;

    float acc[8][8];
#pragma unroll
    for (int i = 0; i < 8; i++)
#pragma unroll
        for (int j = 0; j < 8; j++) acc[i][j] = 0.f;

    const int arow = tid >> 1, ac4 = (tid & 1) * 4;   // A: 128 rows x 8 cols
    const int brow = tid >> 5, bc4 = (tid & 31) * 4;  // B: 8 rows x 128 cols
    const float* Aptr = X + (m0 + arow) * EMB + ac4;
    const float* Bptr = W + (size_t)brow * NQKV + n0 + bc4;

    for (int k0 = 0; k0 < EMB; k0 += 8) {
        float4 av = *(const float4*)(Aptr + k0);
        float4 bv = *(const float4*)(Bptr + (size_t)k0 * NQKV);
        As[ac4 + 0][arow] = av.x;
        As[ac4 + 1][arow] = av.y;
        As[ac4 + 2][arow] = av.z;
        As[ac4 + 3][arow] = av.w;
        *(float4*)&Bs[brow][bc4] = bv;
        __syncthreads();
#pragma unroll
        for (int kk = 0; kk < 8; kk++) {
            float a[8], b[8];
            *(float4*)(a)     = *(const float4*)&As[kk][ty * 4];
            *(float4*)(a + 4) = *(const float4*)&As[kk][64 + ty * 4];
            *(float4*)(b)     = *(const float4*)&Bs[kk][tx * 4];
            *(float4*)(b + 4) = *(const float4*)&Bs[kk][64 + tx * 4];
#pragma unroll
            for (int i = 0; i < 8; i++)
#pragma unroll
                for (int j = 0; j < 8; j++)
                    acc[i][j] = fmaf(a[i], b[j], acc[i][j]);
        }
        __syncthreads();
    }

    // Epilogue: RoPE + scatter. Thread's cols come in 4-aligned groups of 4,
    // so (even,odd) RoPE pairs are intra-thread.
#pragma unroll
    for (int i = 0; i < 8; i++) {
        int row = m0 + ((i < 4) ? (ty * 4 + i) : (64 + ty * 4 + i - 4));
        int b_ = row >> 11;       // / SEQ
        int t_ = row & (SEQ - 1);
#pragma unroll
        for (int jp = 0; jp < 8; jp += 2) {
            int col = n0 + ((jp < 4) ? (tx * 4 + jp) : (64 + tx * 4 + jp - 4));
            float v0 = acc[i][jp], v1 = acc[i][jp + 1];
            int seg = col >> 10;          // 0=q 1=k 2=v
            int jc  = col & 1023;
            int h = jc >> 6, d = jc & 63;
            float* dst = (seg == 0) ? g_q : (seg == 1) ? g_k : g_v;
            int idx = ((b_ * NH + h) * SEQ + t_) * HD + d;
            float2 o2;
            if (seg < 2) {
                float c = cp [t_ * (HD / 2) + (d >> 1)];
                float s = snp[t_ * (HD / 2) + (d >> 1)];
                o2.x = v0 * c - v1 * s;
                o2.y = v0 * s + v1 * c;
            } else {
                o2.x = v0; o2.y = v1;
            }
            *(float2*)&dst[idx] = o2;
        }
    }
}

// ---------------------------------------------------------------------------
// Kernel 2: causal flash attention, fp32. Br=Bc=64, 256 threads, 4x4 microtile.
// Dynamic smem, stride-65 padding (odd stride -> 2-way worst-case conflicts).
// ---------------------------------------------------------------------------
#define LDP 65
#define ATTN_SMEM (4 * 64 * LDP * (int)sizeof(float))   // 66560 B

__global__ __launch_bounds__(256)
void attn_kernel()
{
    extern __shared__ float sm[];
    float* sq  = sm;                 // [r][d]  64xLDP, pre-scaled by 1/8
    float* sk  = sq + 64 * LDP;      // [c][d]
    float* sv  = sk + 64 * LDP;      // [j][d]
    float* spp = sv + 64 * LDP;      // [r][j]  probabilities

    const int qt = gridDim.x - 1 - blockIdx.x;  // big tiles launch first
    const int bh = blockIdx.y;
    const float* Qb = g_q + (size_t)bh * SEQ * HD;
    const float* Kb = g_k + (size_t)bh * SEQ * HD;
    const float* Vb = g_v + (size_t)bh * SEQ * HD;

    const int tid = threadIdx.x;
    const int tx = tid & 15, ty = tid >> 4;
    const int r0 = ty * 4, c0 = tx * 4;
    const float SCALE = 0.125f;  // 1/sqrt(64)

    // Load Q tile (scaled)
#pragma unroll
    for (int it = 0; it < 4; it++) {
        int li = tid + it * 256;
        int row = li >> 4, dg = (li & 15) * 4;
        float4 v = *(const float4*)&Qb[(size_t)(qt * 64 + row) * HD + dg];
        sq[row * LDP + dg + 0] = v.x * SCALE;
        sq[row * LDP + dg + 1] = v.y * SCALE;
        sq[row * LDP + dg + 2] = v.z * SCALE;
        sq[row * LDP + dg + 3] = v.w * SCALE;
    }

    float o[4][4];
    float mi[4], li_[4];
#pragma unroll
    for (int i = 0; i < 4; i++) {
        mi[i] = -1e30f; li_[i] = 0.f;
#pragma unroll
        for (int j = 0; j < 4; j++) o[i][j] = 0.f;
    }

    for (int kt = 0; kt <= qt; kt++) {
        // Load K and V tiles
#pragma unroll
        for (int it = 0; it < 4; it++) {
            int li = tid + it * 256;
            int row = li >> 4, dg = (li & 15) * 4;
            float4 kv = *(const float4*)&Kb[(size_t)(kt * 64 + row) * HD + dg];
            float4 vv = *(const float4*)&Vb[(size_t)(kt * 64 + row) * HD + dg];
            sk[row * LDP + dg + 0] = kv.x;
            sk[row * LDP + dg + 1] = kv.y;
            sk[row * LDP + dg + 2] = kv.z;
            sk[row * LDP + dg + 3] = kv.w;
            sv[row * LDP + dg + 0] = vv.x;
            sv[row * LDP + dg + 1] = vv.y;
            sv[row * LDP + dg + 2] = vv.z;
            sv[row * LDP + dg + 3] = vv.w;
        }
        __syncthreads();

        // S = Q K^T (scaled)
        float s[4][4];
#pragma unroll
        for (int i = 0; i < 4; i++)
#pragma unroll
            for (int j = 0; j < 4; j++) s[i][j] = 0.f;

        for (int d = 0; d < HD; d++) {
            float a0 = sq[(r0 + 0) * LDP + d];
            float a1 = sq[(r0 + 1) * LDP + d];
            float a2 = sq[(r0 + 2) * LDP + d];
            float a3 = sq[(r0 + 3) * LDP + d];
            float b0 = sk[(c0 + 0) * LDP + d];
            float b1 = sk[(c0 + 1) * LDP + d];
            float b2 = sk[(c0 + 2) * LDP + d];
            float b3 = sk[(c0 + 3) * LDP + d];
            s[0][0] = fmaf(a0, b0, s[0][0]); s[0][1] = fmaf(a0, b1, s[0][1]);
            s[0][2] = fmaf(a0, b2, s[0][2]); s[0][3] = fmaf(a0, b3, s[0][3]);
            s[1][0] = fmaf(a1, b0, s[1][0]); s[1][1] = fmaf(a1, b1, s[1][1]);
            s[1][2] = fmaf(a1, b2, s[1][2]); s[1][3] = fmaf(a1, b3, s[1][3]);
            s[2][0] = fmaf(a2, b0, s[2][0]); s[2][1] = fmaf(a2, b1, s[2][1]);
            s[2][2] = fmaf(a2, b2, s[2][2]); s[2][3] = fmaf(a2, b3, s[2][3]);
            s[3][0] = fmaf(a3, b0, s[3][0]); s[3][1] = fmaf(a3, b1, s[3][1]);
            s[3][2] = fmaf(a3, b2, s[3][2]); s[3][3] = fmaf(a3, b3, s[3][3]);
        }

        // Causal mask on diagonal tile
        if (kt == qt) {
#pragma unroll
            for (int i = 0; i < 4; i++)
#pragma unroll
                for (int j = 0; j < 4; j++)
                    if (c0 + j > r0 + i) s[i][j] = -1e30f;
        }

        // Online softmax (row reduce over the 16 tx lanes; lane bit4 = ty&1 untouched)
#pragma unroll
        for (int i = 0; i < 4; i++) {
            float mt = fmaxf(fmaxf(s[i][0], s[i][1]), fmaxf(s[i][2], s[i][3]));
#pragma unroll
            for (int off = 1; off < 16; off <<= 1)
                mt = fmaxf(mt, __shfl_xor_sync(0xffffffffu, mt, off));
            float mn = fmaxf(mi[i], mt);
            float al = __expf(mi[i] - mn);
            mi[i] = mn;
            float rs = 0.f;
#pragma unroll
            for (int j = 0; j < 4; j++) {
                s[i][j] = __expf(s[i][j] - mn);
                rs += s[i][j];
            }
#pragma unroll
            for (int off = 1; off < 16; off <<= 1)
                rs += __shfl_xor_sync(0xffffffffu, rs, off);
            li_[i] = li_[i] * al + rs;
#pragma unroll
            for (int j = 0; j < 4; j++) o[i][j] *= al;
            spp[(r0 + i) * LDP + c0 + 0] = s[i][0];
            spp[(r0 + i) * LDP + c0 + 1] = s[i][1];
            spp[(r0 + i) * LDP + c0 + 2] = s[i][2];
            spp[(r0 + i) * LDP + c0 + 3] = s[i][3];
        }
        __syncthreads();

        // O += P V
        for (int j = 0; j < 64; j++) {
            float p0 = spp[(r0 + 0) * LDP + j];
            float p1 = spp[(r0 + 1) * LDP + j];
            float p2 = spp[(r0 + 2) * LDP + j];
            float p3 = spp[(r0 + 3) * LDP + j];
            float v0 = sv[j * LDP + c0 + 0];
            float v1 = sv[j * LDP + c0 + 1];
            float v2 = sv[j * LDP + c0 + 2];
            float v3 = sv[j * LDP + c0 + 3];
            o[0][0] = fmaf(p0, v0, o[0][0]); o[0][1] = fmaf(p0, v1, o[0][1]);
            o[0][2] = fmaf(p0, v2, o[0][2]); o[0][3] = fmaf(p0, v3, o[0][3]);
            o[1][0] = fmaf(p1, v0, o[1][0]); o[1][1] = fmaf(p1, v1, o[1][1]);
            o[1][2] = fmaf(p1, v2, o[1][2]); o[1][3] = fmaf(p1, v3, o[1][3]);
            o[2][0] = fmaf(p2, v0, o[2][0]); o[2][1] = fmaf(p2, v1, o[2][1]);
            o[2][2] = fmaf(p2, v2, o[2][2]); o[2][3] = fmaf(p2, v3, o[2][3]);
            o[3][0] = fmaf(p3, v0, o[3][0]); o[3][1] = fmaf(p3, v1, o[3][1]);
            o[3][2] = fmaf(p3, v2, o[3][2]); o[3][3] = fmaf(p3, v3, o[3][3]);
        }
        __syncthreads();
    }

    // Epilogue: normalize, write [B,T,C] for the proj GEMM
    const int b_ = bh >> 4, h = bh & 15;
#pragma unroll
    for (int i = 0; i < 4; i++) {
        float inv = 1.f / li_[i];
        int t_ = qt * 64 + r0 + i;
        float4 ov;
        ov.x = o[i][0] * inv; ov.y = o[i][1] * inv;
        ov.z = o[i][2] * inv; ov.w = o[i][3] * inv;
        *(float4*)&g_attn[(size_t)(b_ * SEQ + t_) * EMB + h * HD + c0] = ov;
    }
}

// ---------------------------------------------------------------------------
// Kernel 3: out = attn @ Wproj + bproj  (4096x1024x1024)
// ---------------------------------------------------------------------------
__global__ __launch_bounds__(256)
void proj_kernel(const float* __restrict__ W, const float* __restrict__ bias,
                 float* __restrict__ out)
{
    __shared__ float As[8][128];
    __shared__ float Bs[8][128];
    const int tid = threadIdx.x;
    const int tx = tid & 15, ty = tid >> 4;
    const int m0 = blockIdx.y * 128;
    const int n0 = blockIdx.x * 128;

    float acc[8][8];
#pragma unroll
    for (int i = 0; i < 8; i++)
#pragma unroll
        for (int j = 0; j < 8; j++) acc[i][j] = 0.f;

    const int arow = tid >> 1, ac4 = (tid & 1) * 4;
    const int brow = tid >> 5, bc4 = (tid & 31) * 4;
    const float* Aptr = g_attn + (size_t)(m0 + arow) * EMB + ac4;
    const float* Bptr = W + (size_t)brow * EMB + n0 + bc4;

    for (int k0 = 0; k0 < EMB; k0 += 8) {
        float4 av = *(const float4*)(Aptr + k0);
        float4 bv = *(const float4*)(Bptr + (size_t)k0 * EMB);
        As[ac4 + 0][arow] = av.x;
        As[ac4 + 1][arow] = av.y;
        As[ac4 + 2][arow] = av.z;
        As[ac4 + 3][arow] = av.w;
        *(float4*)&Bs[brow][bc4] = bv;
        __syncthreads();
#pragma unroll
        for (int kk = 0; kk < 8; kk++) {
            float a[8], b[8];
            *(float4*)(a)     = *(const float4*)&As[kk][ty * 4];
            *(float4*)(a + 4) = *(const float4*)&As[kk][64 + ty * 4];
            *(float4*)(b)     = *(const float4*)&Bs[kk][tx * 4];
            *(float4*)(b + 4) = *(const float4*)&Bs[kk][64 + tx * 4];
#pragma unroll
            for (int i = 0; i < 8; i++)
#pragma unroll
                for (int j = 0; j < 8; j++)
                    acc[i][j] = fmaf(a[i], b[j], acc[i][j]);
        }
        __syncthreads();
    }

#pragma unroll
    for (int i = 0; i < 8; i++) {
        int row = m0 + ((i < 4) ? (ty * 4 + i) : (64 + ty * 4 + i - 4));
#pragma unroll
        for (int g = 0; g < 2; g++) {
            int col = n0 + g * 64 + tx * 4;
            float4 ov;
            ov.x = acc[i][g * 4 + 0] + bias[col + 0];
            ov.y = acc[i][g * 4 + 1] + bias[col + 1];
            ov.z = acc[i][g * 4 + 2] + bias[col + 2];
            ov.w = acc[i][g * 4 + 3] + bias[col + 3];
            *(float4*)&out[(size_t)row * EMB + col] = ov;
        }
    }
}

// ---------------------------------------------------------------------------
extern "C" void kernel_launch(void* const* d_in, const int* in_sizes, int n_in,
                              void* d_out, int out_size)
{
    const float* x     = (const float*)d_in[0];
    const float* Wqkv  = (const float*)d_in[1];
    const float* Wproj = (const float*)d_in[2];
    const float* bproj = (const float*)d_in[3];
    const float* cosp  = (const float*)d_in[4];
    const float* sinp  = (const float*)d_in[5];
    float* out = (float*)d_out;

    cudaFuncSetAttribute(attn_kernel,
                         cudaFuncAttributeMaxDynamicSharedMemorySize, ATTN_SMEM);

    qkv_rope_kernel<<<dim3(NQKV / 128, MTOT / 128), 256>>>(x, Wqkv, cosp, sinp);
    attn_kernel<<<dim3(SEQ / 64, BATCH * NH), 256, ATTN_SMEM>>>();
    proj_kernel<<<dim3(EMB / 128, MTOT / 128), 256>>>(Wproj, bproj, out);
}

// round 3
// speedup vs baseline: 1.5749x; 1.5749x over previous
#include <cuda_runtime.h>

#define EMB   1024
#define NH    16
#define HD    64
#define SEQ   2048
#define BATCH 2
#define MTOT  (BATCH*SEQ)      // 4096
#define NQKV  (3*EMB)          // 3072

// Scratch (device globals: no allocation allowed in kernel_launch)
__device__ float g_q[BATCH*NH*SEQ*HD];
__device__ float g_k[BATCH*NH*SEQ*HD];
__device__ float g_v[BATCH*NH*SEQ*HD];
__device__ float g_attn[MTOT*EMB];

// ---------------------------------------------------------------------------
// TF32 helpers
// ---------------------------------------------------------------------------
__device__ __forceinline__ unsigned int f2tf32(float f) {
    unsigned int u;
    asm("cvt.rna.tf32.f32 %0, %1;" : "=r"(u) : "f"(f));
    return u;
}

__device__ __forceinline__ void mma_tf32(float c[4],
                                         const unsigned int a[4],
                                         const unsigned int b[2]) {
    asm volatile(
        "mma.sync.aligned.m16n8k8.row.col.f32.tf32.tf32.f32 "
        "{%0,%1,%2,%3}, {%4,%5,%6,%7}, {%8,%9}, {%0,%1,%2,%3};"
        : "+f"(c[0]), "+f"(c[1]), "+f"(c[2]), "+f"(c[3])
        : "r"(a[0]), "r"(a[1]), "r"(a[2]), "r"(a[3]),
          "r"(b[0]), "r"(b[1]));
}

// Shared tile strides (in 4B words), chosen for conflict-free fragment loads:
// A stride 36 (= 4 mod 32): a-frag banks 4g+c -> 32 distinct
// B stride 136 (= 8 mod 32): b-frag banks 8c+g -> 32 distinct
#define LDA 36
#define LDB 136

// ---------------------------------------------------------------------------
// Kernel 1: QKV = X @ Wqkv via TF32 tensor cores, fused RoPE, scatter [B,H,T,D]
// 128x128 block tile, K-step 32, 256 threads, warp tile 64x32.
// ---------------------------------------------------------------------------
__global__ __launch_bounds__(256)
void qkv_rope_kernel(const float* __restrict__ X, const float* __restrict__ W,
                     const float* __restrict__ cp, const float* __restrict__ snp)
{
    __shared__ unsigned int sA[128 * LDA];   // [m][k] tf32
    __shared__ unsigned int sB[32 * LDB];    // [k][n] tf32

    const int tid  = threadIdx.x;
    const int lane = tid & 31;
    const int warp = tid >> 5;
    const int g = lane >> 2, c = lane & 3;
    const int m_base = (warp & 1) * 64;
    const int n_base = (warp >> 1) * 32;
    const int m0 = blockIdx.y * 128;
    const int n0 = blockIdx.x * 128;

    float acc[4][4][4];   // [mfrag][nfrag][reg]
#pragma unroll
    for (int i = 0; i < 4; i++)
#pragma unroll
        for (int j = 0; j < 4; j++)
#pragma unroll
            for (int r = 0; r < 4; r++) acc[i][j][r] = 0.f;

    for (int k0 = 0; k0 < EMB; k0 += 32) {
        // Load A tile 128x32 (1024 float4, 4 per thread)
#pragma unroll
        for (int it = 0; it < 4; it++) {
            int idx = tid + it * 256;
            int row = idx >> 3, c4 = (idx & 7) * 4;
            float4 v = *(const float4*)&X[(size_t)(m0 + row) * EMB + k0 + c4];
            unsigned int* d = &sA[row * LDA + c4];
            d[0] = f2tf32(v.x); d[1] = f2tf32(v.y);
            d[2] = f2tf32(v.z); d[3] = f2tf32(v.w);
        }
        // Load B tile 32x128 (1024 float4, 4 per thread)
#pragma unroll
        for (int it = 0; it < 4; it++) {
            int idx = tid + it * 256;
            int row = idx >> 5, c4 = (idx & 31) * 4;
            float4 v = *(const float4*)&W[(size_t)(k0 + row) * NQKV + n0 + c4];
            unsigned int* d = &sB[row * LDB + c4];
            d[0] = f2tf32(v.x); d[1] = f2tf32(v.y);
            d[2] = f2tf32(v.z); d[3] = f2tf32(v.w);
        }
        __syncthreads();

#pragma unroll
        for (int ks = 0; ks < 4; ks++) {
            unsigned int a[4][4], b[4][2];
#pragma unroll
            for (int mf = 0; mf < 4; mf++) {
                const unsigned int* pa = &sA[(m_base + mf * 16 + g) * LDA + ks * 8];
                a[mf][0] = pa[c];
                a[mf][1] = pa[8 * LDA + c];
                a[mf][2] = pa[c + 4];
                a[mf][3] = pa[8 * LDA + c + 4];
            }
#pragma unroll
            for (int nf = 0; nf < 4; nf++) {
                const unsigned int* pb = &sB[(ks * 8 + c) * LDB + n_base + nf * 8 + g];
                b[nf][0] = pb[0];
                b[nf][1] = pb[4 * LDB];
            }
#pragma unroll
            for (int mf = 0; mf < 4; mf++)
#pragma unroll
                for (int nf = 0; nf < 4; nf++)
                    mma_tf32(acc[mf][nf], a[mf], b[nf]);
        }
        __syncthreads();
    }

    // Epilogue: RoPE + scatter. C-frag cols come as (2c, 2c+1) pairs.
#pragma unroll
    for (int mf = 0; mf < 4; mf++) {
#pragma unroll
        for (int half = 0; half < 2; half++) {
            int row = m0 + m_base + mf * 16 + g + half * 8;
            int b_ = row >> 11;       // / SEQ
            int t_ = row & (SEQ - 1);
#pragma unroll
            for (int nf = 0; nf < 4; nf++) {
                int col = n0 + n_base + nf * 8 + c * 2;
                float v0 = acc[mf][nf][half * 2 + 0];
                float v1 = acc[mf][nf][half * 2 + 1];
                int seg = col >> 10;          // 0=q 1=k 2=v
                int jc  = col & 1023;
                int h = jc >> 6, d = jc & 63;
                float* dst = (seg == 0) ? g_q : (seg == 1) ? g_k : g_v;
                int idx = ((b_ * NH + h) * SEQ + t_) * HD + d;
                float2 o2;
                if (seg < 2) {
                    float cc = cp [t_ * (HD / 2) + (d >> 1)];
                    float ss = snp[t_ * (HD / 2) + (d >> 1)];
                    o2.x = v0 * cc - v1 * ss;
                    o2.y = v0 * ss + v1 * cc;
                } else {
                    o2.x = v0; o2.y = v1;
                }
                *(float2*)&dst[idx] = o2;
            }
        }
    }
}

// ---------------------------------------------------------------------------
// Kernel 2: causal flash attention, fp32. Br=Bc=64, 256 threads, 4x4 microtile.
// (unchanged from the passing round-1 kernel)
// ---------------------------------------------------------------------------
#define LDP 65
#define ATTN_SMEM (4 * 64 * LDP * (int)sizeof(float))   // 66560 B

__global__ __launch_bounds__(256)
void attn_kernel()
{
    extern __shared__ float sm[];
    float* sq  = sm;                 // [r][d]  64xLDP, pre-scaled by 1/8
    float* sk  = sq + 64 * LDP;      // [c][d]
    float* sv  = sk + 64 * LDP;      // [j][d]
    float* spp = sv + 64 * LDP;      // [r][j]  probabilities

    const int qt = gridDim.x - 1 - blockIdx.x;  // big tiles launch first
    const int bh = blockIdx.y;
    const float* Qb = g_q + (size_t)bh * SEQ * HD;
    const float* Kb = g_k + (size_t)bh * SEQ * HD;
    const float* Vb = g_v + (size_t)bh * SEQ * HD;

    const int tid = threadIdx.x;
    const int tx = tid & 15, ty = tid >> 4;
    const int r0 = ty * 4, c0 = tx * 4;
    const float SCALE = 0.125f;  // 1/sqrt(64)

#pragma unroll
    for (int it = 0; it < 4; it++) {
        int li = tid + it * 256;
        int row = li >> 4, dg = (li & 15) * 4;
        float4 v = *(const float4*)&Qb[(size_t)(qt * 64 + row) * HD + dg];
        sq[row * LDP + dg + 0] = v.x * SCALE;
        sq[row * LDP + dg + 1] = v.y * SCALE;
        sq[row * LDP + dg + 2] = v.z * SCALE;
        sq[row * LDP + dg + 3] = v.w * SCALE;
    }

    float o[4][4];
    float mi[4], li_[4];
#pragma unroll
    for (int i = 0; i < 4; i++) {
        mi[i] = -1e30f; li_[i] = 0.f;
#pragma unroll
        for (int j = 0; j < 4; j++) o[i][j] = 0.f;
    }

    for (int kt = 0; kt <= qt; kt++) {
#pragma unroll
        for (int it = 0; it < 4; it++) {
            int li = tid + it * 256;
            int row = li >> 4, dg = (li & 15) * 4;
            float4 kv = *(const float4*)&Kb[(size_t)(kt * 64 + row) * HD + dg];
            float4 vv = *(const float4*)&Vb[(size_t)(kt * 64 + row) * HD + dg];
            sk[row * LDP + dg + 0] = kv.x;
            sk[row * LDP + dg + 1] = kv.y;
            sk[row * LDP + dg + 2] = kv.z;
            sk[row * LDP + dg + 3] = kv.w;
            sv[row * LDP + dg + 0] = vv.x;
            sv[row * LDP + dg + 1] = vv.y;
            sv[row * LDP + dg + 2] = vv.z;
            sv[row * LDP + dg + 3] = vv.w;
        }
        __syncthreads();

        float s[4][4];
#pragma unroll
        for (int i = 0; i < 4; i++)
#pragma unroll
            for (int j = 0; j < 4; j++) s[i][j] = 0.f;

        for (int d = 0; d < HD; d++) {
            float a0 = sq[(r0 + 0) * LDP + d];
            float a1 = sq[(r0 + 1) * LDP + d];
            float a2 = sq[(r0 + 2) * LDP + d];
            float a3 = sq[(r0 + 3) * LDP + d];
            float b0 = sk[(c0 + 0) * LDP + d];
            float b1 = sk[(c0 + 1) * LDP + d];
            float b2 = sk[(c0 + 2) * LDP + d];
            float b3 = sk[(c0 + 3) * LDP + d];
            s[0][0] = fmaf(a0, b0, s[0][0]); s[0][1] = fmaf(a0, b1, s[0][1]);
            s[0][2] = fmaf(a0, b2, s[0][2]); s[0][3] = fmaf(a0, b3, s[0][3]);
            s[1][0] = fmaf(a1, b0, s[1][0]); s[1][1] = fmaf(a1, b1, s[1][1]);
            s[1][2] = fmaf(a1, b2, s[1][2]); s[1][3] = fmaf(a1, b3, s[1][3]);
            s[2][0] = fmaf(a2, b0, s[2][0]); s[2][1] = fmaf(a2, b1, s[2][1]);
            s[2][2] = fmaf(a2, b2, s[2][2]); s[2][3] = fmaf(a2, b3, s[2][3]);
            s[3][0] = fmaf(a3, b0, s[3][0]); s[3][1] = fmaf(a3, b1, s[3][1]);
            s[3][2] = fmaf(a3, b2, s[3][2]); s[3][3] = fmaf(a3, b3, s[3][3]);
        }

        if (kt == qt) {
#pragma unroll
            for (int i = 0; i < 4; i++)
#pragma unroll
                for (int j = 0; j < 4; j++)
                    if (c0 + j > r0 + i) s[i][j] = -1e30f;
        }

#pragma unroll
        for (int i = 0; i < 4; i++) {
            float mt = fmaxf(fmaxf(s[i][0], s[i][1]), fmaxf(s[i][2], s[i][3]));
#pragma unroll
            for (int off = 1; off < 16; off <<= 1)
                mt = fmaxf(mt, __shfl_xor_sync(0xffffffffu, mt, off));
            float mn = fmaxf(mi[i], mt);
            float al = __expf(mi[i] - mn);
            mi[i] = mn;
            float rs = 0.f;
#pragma unroll
            for (int j = 0; j < 4; j++) {
                s[i][j] = __expf(s[i][j] - mn);
                rs += s[i][j];
            }
#pragma unroll
            for (int off = 1; off < 16; off <<= 1)
                rs += __shfl_xor_sync(0xffffffffu, rs, off);
            li_[i] = li_[i] * al + rs;
#pragma unroll
            for (int j = 0; j < 4; j++) o[i][j] *= al;
            spp[(r0 + i) * LDP + c0 + 0] = s[i][0];
            spp[(r0 + i) * LDP + c0 + 1] = s[i][1];
            spp[(r0 + i) * LDP + c0 + 2] = s[i][2];
            spp[(r0 + i) * LDP + c0 + 3] = s[i][3];
        }
        __syncthreads();

        for (int j = 0; j < 64; j++) {
            float p0 = spp[(r0 + 0) * LDP + j];
            float p1 = spp[(r0 + 1) * LDP + j];
            float p2 = spp[(r0 + 2) * LDP + j];
            float p3 = spp[(r0 + 3) * LDP + j];
            float v0 = sv[j * LDP + c0 + 0];
            float v1 = sv[j * LDP + c0 + 1];
            float v2 = sv[j * LDP + c0 + 2];
            float v3 = sv[j * LDP + c0 + 3];
            o[0][0] = fmaf(p0, v0, o[0][0]); o[0][1] = fmaf(p0, v1, o[0][1]);
            o[0][2] = fmaf(p0, v2, o[0][2]); o[0][3] = fmaf(p0, v3, o[0][3]);
            o[1][0] = fmaf(p1, v0, o[1][0]); o[1][1] = fmaf(p1, v1, o[1][1]);
            o[1][2] = fmaf(p1, v2, o[1][2]); o[1][3] = fmaf(p1, v3, o[1][3]);
            o[2][0] = fmaf(p2, v0, o[2][0]); o[2][1] = fmaf(p2, v1, o[2][1]);
            o[2][2] = fmaf(p2, v2, o[2][2]); o[2][3] = fmaf(p2, v3, o[2][3]);
            o[3][0] = fmaf(p3, v0, o[3][0]); o[3][1] = fmaf(p3, v1, o[3][1]);
            o[3][2] = fmaf(p3, v2, o[3][2]); o[3][3] = fmaf(p3, v3, o[3][3]);
        }
        __syncthreads();
    }

    const int b_ = bh >> 4, h = bh & 15;
#pragma unroll
    for (int i = 0; i < 4; i++) {
        float inv = 1.f / li_[i];
        int t_ = qt * 64 + r0 + i;
        float4 ov;
        ov.x = o[i][0] * inv; ov.y = o[i][1] * inv;
        ov.z = o[i][2] * inv; ov.w = o[i][3] * inv;
        *(float4*)&g_attn[(size_t)(b_ * SEQ + t_) * EMB + h * HD + c0] = ov;
    }
}

// ---------------------------------------------------------------------------
// Kernel 3: out = attn @ Wproj + bproj via TF32 tensor cores (4096x1024x1024)
// ---------------------------------------------------------------------------
__global__ __launch_bounds__(256)
void proj_kernel(const float* __restrict__ W, const float* __restrict__ bias,
                 float* __restrict__ out)
{
    __shared__ unsigned int sA[128 * LDA];
    __shared__ unsigned int sB[32 * LDB];

    const int tid  = threadIdx.x;
    const int lane = tid & 31;
    const int warp = tid >> 5;
    const int g = lane >> 2, c = lane & 3;
    const int m_base = (warp & 1) * 64;
    const int n_base = (warp >> 1) * 32;
    const int m0 = blockIdx.y * 128;
    const int n0 = blockIdx.x * 128;

    float acc[4][4][4];
#pragma unroll
    for (int i = 0; i < 4; i++)
#pragma unroll
        for (int j = 0; j < 4; j++)
#pragma unroll
            for (int r = 0; r < 4; r++) acc[i][j][r] = 0.f;

    for (int k0 = 0; k0 < EMB; k0 += 32) {
#pragma unroll
        for (int it = 0; it < 4; it++) {
            int idx = tid + it * 256;
            int row = idx >> 3, c4 = (idx & 7) * 4;
            float4 v = *(const float4*)&g_attn[(size_t)(m0 + row) * EMB + k0 + c4];
            unsigned int* d = &sA[row * LDA + c4];
            d[0] = f2tf32(v.x); d[1] = f2tf32(v.y);
            d[2] = f2tf32(v.z); d[3] = f2tf32(v.w);
        }
#pragma unroll
        for (int it = 0; it < 4; it++) {
            int idx = tid + it * 256;
            int row = idx >> 5, c4 = (idx & 31) * 4;
            float4 v = *(const float4*)&W[(size_t)(k0 + row) * EMB + n0 + c4];
            unsigned int* d = &sB[row * LDB + c4];
            d[0] = f2tf32(v.x); d[1] = f2tf32(v.y);
            d[2] = f2tf32(v.z); d[3] = f2tf32(v.w);
        }
        __syncthreads();

#pragma unroll
        for (int ks = 0; ks < 4; ks++) {
            unsigned int a[4][4], b[4][2];
#pragma unroll
            for (int mf = 0; mf < 4; mf++) {
                const unsigned int* pa = &sA[(m_base + mf * 16 + g) * LDA + ks * 8];
                a[mf][0] = pa[c];
                a[mf][1] = pa[8 * LDA + c];
                a[mf][2] = pa[c + 4];
                a[mf][3] = pa[8 * LDA + c + 4];
            }
#pragma unroll
            for (int nf = 0; nf < 4; nf++) {
                const unsigned int* pb = &sB[(ks * 8 + c) * LDB + n_base + nf * 8 + g];
                b[nf][0] = pb[0];
                b[nf][1] = pb[4 * LDB];
            }
#pragma unroll
            for (int mf = 0; mf < 4; mf++)
#pragma unroll
                for (int nf = 0; nf < 4; nf++)
                    mma_tf32(acc[mf][nf], a[mf], b[nf]);
        }
        __syncthreads();
    }

#pragma unroll
    for (int mf = 0; mf < 4; mf++) {
#pragma unroll
        for (int half = 0; half < 2; half++) {
            int row = m0 + m_base + mf * 16 + g + half * 8;
#pragma unroll
            for (int nf = 0; nf < 4; nf++) {
                int col = n0 + n_base + nf * 8 + c * 2;
                float2 o2;
                o2.x = acc[mf][nf][half * 2 + 0] + bias[col + 0];
                o2.y = acc[mf][nf][half * 2 + 1] + bias[col + 1];
                *(float2*)&out[(size_t)row * EMB + col] = o2;
            }
        }
    }
}

// ---------------------------------------------------------------------------
extern "C" void kernel_launch(void* const* d_in, const int* in_sizes, int n_in,
                              void* d_out, int out_size)
{
    const float* x     = (const float*)d_in[0];
    const float* Wqkv  = (const float*)d_in[1];
    const float* Wproj = (const float*)d_in[2];
    const float* bproj = (const float*)d_in[3];
    const float* cosp  = (const float*)d_in[4];
    const float* sinp  = (const float*)d_in[5];
    float* out = (float*)d_out;

    cudaFuncSetAttribute(attn_kernel,
                         cudaFuncAttributeMaxDynamicSharedMemorySize, ATTN_SMEM);

    qkv_rope_kernel<<<dim3(NQKV / 128, MTOT / 128), 256>>>(x, Wqkv, cosp, sinp);
    attn_kernel<<<dim3(SEQ / 64, BATCH * NH), 256, ATTN_SMEM>>>();
    proj_kernel<<<dim3(EMB / 128, MTOT / 128), 256>>>(Wproj, bproj, out);
}

// round 6
// speedup vs baseline: 3.3852x; 2.1495x over previous
#include <cuda_runtime.h>

#define EMB   1024
#define NH    16
#define HD    64
#define SEQ   2048
#define BATCH 2
#define MTOT  (BATCH*SEQ)      // 4096
#define NQKV  (3*EMB)          // 3072

// Scratch (device globals: no allocation allowed in kernel_launch)
__device__ float g_q[BATCH*NH*SEQ*HD];
__device__ float g_k[BATCH*NH*SEQ*HD];
__device__ float g_v[BATCH*NH*SEQ*HD];
__device__ float g_attn[MTOT*EMB];

// ---------------------------------------------------------------------------
// TF32 helpers
// ---------------------------------------------------------------------------
__device__ __forceinline__ unsigned int f2tf32(float f) {
    unsigned int u;
    asm("cvt.rna.tf32.f32 %0, %1;" : "=r"(u) : "f"(f));
    return u;
}

__device__ __forceinline__ void mma_tf32(float c[4],
                                         const unsigned int a[4],
                                         const unsigned int b[2]) {
    asm volatile(
        "mma.sync.aligned.m16n8k8.row.col.f32.tf32.tf32.f32 "
        "{%0,%1,%2,%3}, {%4,%5,%6,%7}, {%8,%9}, {%0,%1,%2,%3};"
        : "+f"(c[0]), "+f"(c[1]), "+f"(c[2]), "+f"(c[3])
        : "r"(a[0]), "r"(a[1]), "r"(a[2]), "r"(a[3]),
          "r"(b[0]), "r"(b[1]));
}

// GEMM tile strides (words): A stride 36 (=4 mod 32), B stride 136 (=8 mod 32)
#define LDA 36
#define LDB 136

// ---------------------------------------------------------------------------
// Kernel 1: QKV = X @ Wqkv via TF32 tensor cores, fused RoPE, scatter [B,H,T,D]
// ---------------------------------------------------------------------------
__global__ __launch_bounds__(256)
void qkv_rope_kernel(const float* __restrict__ X, const float* __restrict__ W,
                     const float* __restrict__ cp, const float* __restrict__ snp)
{
    __shared__ unsigned int sA[128 * LDA];   // [m][k] tf32
    __shared__ unsigned int sB[32 * LDB];    // [k][n] tf32

    const int tid  = threadIdx.x;
    const int lane = tid & 31;
    const int warp = tid >> 5;
    const int g = lane >> 2, c = lane & 3;
    const int m_base = (warp & 1) * 64;
    const int n_base = (warp >> 1) * 32;
    const int m0 = blockIdx.y * 128;
    const int n0 = blockIdx.x * 128;

    float acc[4][4][4];
#pragma unroll
    for (int i = 0; i < 4; i++)
#pragma unroll
        for (int j = 0; j < 4; j++)
#pragma unroll
            for (int r = 0; r < 4; r++) acc[i][j][r] = 0.f;

    for (int k0 = 0; k0 < EMB; k0 += 32) {
#pragma unroll
        for (int it = 0; it < 4; it++) {
            int idx = tid + it * 256;
            int row = idx >> 3, c4 = (idx & 7) * 4;
            float4 v = *(const float4*)&X[(size_t)(m0 + row) * EMB + k0 + c4];
            unsigned int* d = &sA[row * LDA + c4];
            d[0] = f2tf32(v.x); d[1] = f2tf32(v.y);
            d[2] = f2tf32(v.z); d[3] = f2tf32(v.w);
        }
#pragma unroll
        for (int it = 0; it < 4; it++) {
            int idx = tid + it * 256;
            int row = idx >> 5, c4 = (idx & 31) * 4;
            float4 v = *(const float4*)&W[(size_t)(k0 + row) * NQKV + n0 + c4];
            unsigned int* d = &sB[row * LDB + c4];
            d[0] = f2tf32(v.x); d[1] = f2tf32(v.y);
            d[2] = f2tf32(v.z); d[3] = f2tf32(v.w);
        }
        __syncthreads();

#pragma unroll
        for (int ks = 0; ks < 4; ks++) {
            unsigned int a[4][4], b[4][2];
#pragma unroll
            for (int mf = 0; mf < 4; mf++) {
                const unsigned int* pa = &sA[(m_base + mf * 16 + g) * LDA + ks * 8];
                a[mf][0] = pa[c];
                a[mf][1] = pa[8 * LDA + c];
                a[mf][2] = pa[c + 4];
                a[mf][3] = pa[8 * LDA + c + 4];
            }
#pragma unroll
            for (int nf = 0; nf < 4; nf++) {
                const unsigned int* pb = &sB[(ks * 8 + c) * LDB + n_base + nf * 8 + g];
                b[nf][0] = pb[0];
                b[nf][1] = pb[4 * LDB];
            }
#pragma unroll
            for (int mf = 0; mf < 4; mf++)
#pragma unroll
                for (int nf = 0; nf < 4; nf++)
                    mma_tf32(acc[mf][nf], a[mf], b[nf]);
        }
        __syncthreads();
    }

#pragma unroll
    for (int mf = 0; mf < 4; mf++) {
#pragma unroll
        for (int half = 0; half < 2; half++) {
            int row = m0 + m_base + mf * 16 + g + half * 8;
            int b_ = row >> 11;
            int t_ = row & (SEQ - 1);
#pragma unroll
            for (int nf = 0; nf < 4; nf++) {
                int col = n0 + n_base + nf * 8 + c * 2;
                float v0 = acc[mf][nf][half * 2 + 0];
                float v1 = acc[mf][nf][half * 2 + 1];
                int seg = col >> 10;
                int jc  = col & 1023;
                int h = jc >> 6, d = jc & 63;
                float* dst = (seg == 0) ? g_q : (seg == 1) ? g_k : g_v;
                int idx = ((b_ * NH + h) * SEQ + t_) * HD + d;
                float2 o2;
                if (seg < 2) {
                    float cc = cp [t_ * (HD / 2) + (d >> 1)];
                    float ss = snp[t_ * (HD / 2) + (d >> 1)];
                    o2.x = v0 * cc - v1 * ss;
                    o2.y = v0 * ss + v1 * cc;
                } else {
                    o2.x = v0; o2.y = v1;
                }
                *(float2*)&dst[idx] = o2;
            }
        }
    }
}

// ---------------------------------------------------------------------------
// Kernel 2: causal flash attention, TF32 tensor cores.
// Block = 64 q-rows x one (b,h). 128 threads, 4 warps x 16 rows.
// Q fragments register-resident; sq smem reused as P buffer.
// ---------------------------------------------------------------------------
#define LDQ 68   // 4 mod 32: A-style frags conflict-free
#define LDK 68
#define LDV 72   // 8 mod 32: B-style frags conflict-free
#define ATTN_SMEM ((64*LDQ + 64*LDK + 64*LDV) * 4)   // 53248 B

__global__ __launch_bounds__(128)
void attn_kernel()
{
    extern __shared__ unsigned int smu[];
    unsigned int* sq = smu;             // Q then P (aliased)
    unsigned int* sk = sq + 64 * LDQ;
    unsigned int* sv = sk + 64 * LDK;

    const int qt = gridDim.x - 1 - blockIdx.x;   // big tiles first
    const int bh = blockIdx.y;
    const float* Qb = g_q + (size_t)bh * SEQ * HD;
    const float* Kb = g_k + (size_t)bh * SEQ * HD;
    const float* Vb = g_v + (size_t)bh * SEQ * HD;

    const int tid  = threadIdx.x;
    const int lane = tid & 31;
    const int warp = tid >> 5;
    const int g = lane >> 2, c = lane & 3;
    const int rw = warp * 16;
    const float SCALE = 0.125f;   // 1/sqrt(64)

    // Load Q tile (scaled, tf32)
#pragma unroll
    for (int it = 0; it < 8; it++) {
        int idx = tid + it * 128;
        int row = idx >> 4, c4 = (idx & 15) * 4;
        float4 v = *(const float4*)&Qb[(size_t)(qt * 64 + row) * HD + c4];
        unsigned int* d = &sq[row * LDQ + c4];
        d[0] = f2tf32(v.x * SCALE); d[1] = f2tf32(v.y * SCALE);
        d[2] = f2tf32(v.z * SCALE); d[3] = f2tf32(v.w * SCALE);
    }
    __syncthreads();

    // Q fragments -> registers
    unsigned int qf[8][4];
#pragma unroll
    for (int kf = 0; kf < 8; kf++) {
        const unsigned int* p = &sq[(rw + g) * LDQ + kf * 8];
        qf[kf][0] = p[c];
        qf[kf][1] = p[8 * LDQ + c];
        qf[kf][2] = p[c + 4];
        qf[kf][3] = p[8 * LDQ + c + 4];
    }
    __syncthreads();   // sq now reusable as P buffer

    float oacc[8][4];
#pragma unroll
    for (int df = 0; df < 8; df++)
#pragma unroll
        for (int r = 0; r < 4; r++) oacc[df][r] = 0.f;
    float mi0 = -1e30f, mi1 = -1e30f, li0 = 0.f, li1 = 0.f;

    for (int kt = 0; kt <= qt; kt++) {
        // Load K,V tiles (tf32)
#pragma unroll
        for (int it = 0; it < 8; it++) {
            int idx = tid + it * 128;
            int row = idx >> 4, c4 = (idx & 15) * 4;
            float4 kv = *(const float4*)&Kb[(size_t)(kt * 64 + row) * HD + c4];
            float4 vv = *(const float4*)&Vb[(size_t)(kt * 64 + row) * HD + c4];
            unsigned int* dk = &sk[row * LDK + c4];
            dk[0] = f2tf32(kv.x); dk[1] = f2tf32(kv.y);
            dk[2] = f2tf32(kv.z); dk[3] = f2tf32(kv.w);
            unsigned int* dv = &sv[row * LDV + c4];
            dv[0] = f2tf32(vv.x); dv[1] = f2tf32(vv.y);
            dv[2] = f2tf32(vv.z); dv[3] = f2tf32(vv.w);
        }
        __syncthreads();

        // S = Q K^T  (warp: 16 rows x 64 cols)
        float sacc[8][4];
#pragma unroll
        for (int nf = 0; nf < 8; nf++)
#pragma unroll
            for (int r = 0; r < 4; r++) sacc[nf][r] = 0.f;

#pragma unroll
        for (int nf = 0; nf < 8; nf++) {
#pragma unroll
            for (int kf = 0; kf < 8; kf++) {
                unsigned int b[2];
                const unsigned int* pb = &sk[(nf * 8 + g) * LDK + kf * 8];
                b[0] = pb[c];
                b[1] = pb[c + 4];
                mma_tf32(sacc[nf], qf[kf], b);
            }
        }

        // Causal mask on diagonal tile (local coords)
        if (kt == qt) {
            int r0 = rw + g, r1 = rw + g + 8;
#pragma unroll
            for (int nf = 0; nf < 8; nf++) {
                int col0 = nf * 8 + 2 * c, col1 = col0 + 1;
                if (col0 > r0) sacc[nf][0] = -1e30f;
                if (col1 > r0) sacc[nf][1] = -1e30f;
                if (col0 > r1) sacc[nf][2] = -1e30f;
                if (col1 > r1) sacc[nf][3] = -1e30f;
            }
        }

        // Online softmax (rows g and g+8; reduce over quad lanes c=0..3)
        float m0 = -1e30f, m1 = -1e30f;
#pragma unroll
        for (int nf = 0; nf < 8; nf++) {
            m0 = fmaxf(m0, fmaxf(sacc[nf][0], sacc[nf][1]));
            m1 = fmaxf(m1, fmaxf(sacc[nf][2], sacc[nf][3]));
        }
        m0 = fmaxf(m0, __shfl_xor_sync(0xffffffffu, m0, 1));
        m0 = fmaxf(m0, __shfl_xor_sync(0xffffffffu, m0, 2));
        m1 = fmaxf(m1, __shfl_xor_sync(0xffffffffu, m1, 1));
        m1 = fmaxf(m1, __shfl_xor_sync(0xffffffffu, m1, 2));
        float mn0 = fmaxf(mi0, m0), mn1 = fmaxf(mi1, m1);
        float al0 = __expf(mi0 - mn0), al1 = __expf(mi1 - mn1);
        mi0 = mn0; mi1 = mn1;

        float rs0 = 0.f, rs1 = 0.f;
#pragma unroll
        for (int nf = 0; nf < 8; nf++) {
            sacc[nf][0] = __expf(sacc[nf][0] - mn0);
            sacc[nf][1] = __expf(sacc[nf][1] - mn0);
            sacc[nf][2] = __expf(sacc[nf][2] - mn1);
            sacc[nf][3] = __expf(sacc[nf][3] - mn1);
            rs0 += sacc[nf][0] + sacc[nf][1];
            rs1 += sacc[nf][2] + sacc[nf][3];
        }
        rs0 += __shfl_xor_sync(0xffffffffu, rs0, 1);
        rs0 += __shfl_xor_sync(0xffffffffu, rs0, 2);
        rs1 += __shfl_xor_sync(0xffffffffu, rs1, 1);
        rs1 += __shfl_xor_sync(0xffffffffu, rs1, 2);
        li0 = li0 * al0 + rs0;
        li1 = li1 * al1 + rs1;
#pragma unroll
        for (int df = 0; df < 8; df++) {
            oacc[df][0] *= al0; oacc[df][1] *= al0;
            oacc[df][2] *= al1; oacc[df][3] *= al1;
        }

        // P -> smem (tf32), per-warp region (rows rw..rw+15)
#pragma unroll
        for (int nf = 0; nf < 8; nf++) {
            sq[(rw + g)     * LDQ + nf * 8 + 2 * c]     = f2tf32(sacc[nf][0]);
            sq[(rw + g)     * LDQ + nf * 8 + 2 * c + 1] = f2tf32(sacc[nf][1]);
            sq[(rw + g + 8) * LDQ + nf * 8 + 2 * c]     = f2tf32(sacc[nf][2]);
            sq[(rw + g + 8) * LDQ + nf * 8 + 2 * c + 1] = f2tf32(sacc[nf][3]);
        }
        __syncwarp();

        // O += P V
#pragma unroll
        for (int jf = 0; jf < 8; jf++) {
            unsigned int pa[4];
            const unsigned int* pp = &sq[(rw + g) * LDQ + jf * 8];
            pa[0] = pp[c];
            pa[1] = pp[8 * LDQ + c];
            pa[2] = pp[c + 4];
            pa[3] = pp[8 * LDQ + c + 4];
#pragma unroll
            for (int df = 0; df < 8; df++) {
                unsigned int b[2];
                const unsigned int* pv = &sv[(jf * 8 + c) * LDV + df * 8 + g];
                b[0] = pv[0];
                b[1] = pv[4 * LDV];
                mma_tf32(oacc[df], pa, b);
            }
        }
        __syncthreads();   // protect sk/sv before next iteration's load
    }

    // Epilogue: normalize, write [B,T,C]
    const int b_ = bh >> 4, h = bh & 15;
    const float inv0 = 1.f / li0, inv1 = 1.f / li1;
    const int t0 = qt * 64 + rw + g, t1 = t0 + 8;
#pragma unroll
    for (int df = 0; df < 8; df++) {
        int col = h * HD + df * 8 + 2 * c;
        float2 o0, o1;
        o0.x = oacc[df][0] * inv0; o0.y = oacc[df][1] * inv0;
        o1.x = oacc[df][2] * inv1; o1.y = oacc[df][3] * inv1;
        *(float2*)&g_attn[(size_t)(b_ * SEQ + t0) * EMB + col] = o0;
        *(float2*)&g_attn[(size_t)(b_ * SEQ + t1) * EMB + col] = o1;
    }
}

// ---------------------------------------------------------------------------
// Kernel 3: out = attn @ Wproj + bproj via TF32 tensor cores (4096x1024x1024)
// ---------------------------------------------------------------------------
__global__ __launch_bounds__(256)
void proj_kernel(const float* __restrict__ W, const float* __restrict__ bias,
                 float* __restrict__ out)
{
    __shared__ unsigned int sA[128 * LDA];
    __shared__ unsigned int sB[32 * LDB];

    const int tid  = threadIdx.x;
    const int lane = tid & 31;
    const int warp = tid >> 5;
    const int g = lane >> 2, c = lane & 3;
    const int m_base = (warp & 1) * 64;
    const int n_base = (warp >> 1) * 32;
    const int m0 = blockIdx.y * 128;
    const int n0 = blockIdx.x * 128;

    float acc[4][4][4];
#pragma unroll
    for (int i = 0; i < 4; i++)
#pragma unroll
        for (int j = 0; j < 4; j++)
#pragma unroll
            for (int r = 0; r < 4; r++) acc[i][j][r] = 0.f;

    for (int k0 = 0; k0 < EMB; k0 += 32) {
#pragma unroll
        for (int it = 0; it < 4; it++) {
            int idx = tid + it * 256;
            int row = idx >> 3, c4 = (idx & 7) * 4;
            float4 v = *(const float4*)&g_attn[(size_t)(m0 + row) * EMB + k0 + c4];
            unsigned int* d = &sA[row * LDA + c4];
            d[0] = f2tf32(v.x); d[1] = f2tf32(v.y);
            d[2] = f2tf32(v.z); d[3] = f2tf32(v.w);
        }
#pragma unroll
        for (int it = 0; it < 4; it++) {
            int idx = tid + it * 256;
            int row = idx >> 5, c4 = (idx & 31) * 4;
            float4 v = *(const float4*)&W[(size_t)(k0 + row) * EMB + n0 + c4];
            unsigned int* d = &sB[row * LDB + c4];
            d[0] = f2tf32(v.x); d[1] = f2tf32(v.y);
            d[2] = f2tf32(v.z); d[3] = f2tf32(v.w);
        }
        __syncthreads();

#pragma unroll
        for (int ks = 0; ks < 4; ks++) {
            unsigned int a[4][4], b[4][2];
#pragma unroll
            for (int mf = 0; mf < 4; mf++) {
                const unsigned int* pa = &sA[(m_base + mf * 16 + g) * LDA + ks * 8];
                a[mf][0] = pa[c];
                a[mf][1] = pa[8 * LDA + c];
                a[mf][2] = pa[c + 4];
                a[mf][3] = pa[8 * LDA + c + 4];
            }
#pragma unroll
            for (int nf = 0; nf < 4; nf++) {
                const unsigned int* pb = &sB[(ks * 8 + c) * LDB + n_base + nf * 8 + g];
                b[nf][0] = pb[0];
                b[nf][1] = pb[4 * LDB];
            }
#pragma unroll
            for (int mf = 0; mf < 4; mf++)
#pragma unroll
                for (int nf = 0; nf < 4; nf++)
                    mma_tf32(acc[mf][nf], a[mf], b[nf]);
        }
        __syncthreads();
    }

#pragma unroll
    for (int mf = 0; mf < 4; mf++) {
#pragma unroll
        for (int half = 0; half < 2; half++) {
            int row = m0 + m_base + mf * 16 + g + half * 8;
#pragma unroll
            for (int nf = 0; nf < 4; nf++) {
                int col = n0 + n_base + nf * 8 + c * 2;
                float2 o2;
                o2.x = acc[mf][nf][half * 2 + 0] + bias[col + 0];
                o2.y = acc[mf][nf][half * 2 + 1] + bias[col + 1];
                *(float2*)&out[(size_t)row * EMB + col] = o2;
            }
        }
    }
}

// ---------------------------------------------------------------------------
extern "C" void kernel_launch(void* const* d_in, const int* in_sizes, int n_in,
                              void* d_out, int out_size)
{
    const float* x     = (const float*)d_in[0];
    const float* Wqkv  = (const float*)d_in[1];
    const float* Wproj = (const float*)d_in[2];
    const float* bproj = (const float*)d_in[3];
    const float* cosp  = (const float*)d_in[4];
    const float* sinp  = (const float*)d_in[5];
    float* out = (float*)d_out;

    cudaFuncSetAttribute(attn_kernel,
                         cudaFuncAttributeMaxDynamicSharedMemorySize, ATTN_SMEM);

    qkv_rope_kernel<<<dim3(NQKV / 128, MTOT / 128), 256>>>(x, Wqkv, cosp, sinp);
    attn_kernel<<<dim3(SEQ / 64, BATCH * NH), 128, ATTN_SMEM>>>();
    proj_kernel<<<dim3(EMB / 128, MTOT / 128), 256>>>(Wproj, bproj, out);
}

// round 7
// speedup vs baseline: 3.4780x; 1.0274x over previous
#include <cuda_runtime.h>

#define EMB   1024
#define NH    16
#define HD    64
#define SEQ   2048
#define BATCH 2
#define MTOT  (BATCH*SEQ)      // 4096
#define NQKV  (3*EMB)          // 3072

// Scratch (device globals: no allocation allowed in kernel_launch)
__device__ float g_q[BATCH*NH*SEQ*HD];
__device__ float g_k[BATCH*NH*SEQ*HD];
__device__ float g_v[BATCH*NH*SEQ*HD];
__device__ float g_attn[MTOT*EMB];

// ---------------------------------------------------------------------------
// TF32 helpers
// ---------------------------------------------------------------------------
__device__ __forceinline__ unsigned int f2tf32(float f) {
    unsigned int u;
    asm("cvt.rna.tf32.f32 %0, %1;" : "=r"(u) : "f"(f));
    return u;
}

__device__ __forceinline__ void mma_tf32(float c[4],
                                         const unsigned int a[4],
                                         const unsigned int b[2]) {
    asm volatile(
        "mma.sync.aligned.m16n8k8.row.col.f32.tf32.tf32.f32 "
        "{%0,%1,%2,%3}, {%4,%5,%6,%7}, {%8,%9}, {%0,%1,%2,%3};"
        : "+f"(c[0]), "+f"(c[1]), "+f"(c[2]), "+f"(c[3])
        : "r"(a[0]), "r"(a[1]), "r"(a[2]), "r"(a[3]),
          "r"(b[0]), "r"(b[1]));
}

__device__ __forceinline__ void cp_async16(void* smem_dst, const void* gsrc) {
    unsigned int d = (unsigned int)__cvta_generic_to_shared(smem_dst);
    asm volatile("cp.async.cg.shared.global [%0], [%1], 16;" :: "r"(d), "l"(gsrc));
}

// GEMM tile strides (words): A stride 36 (=4 mod 32), B stride 136 (=8 mod 32)
#define LDA 36
#define LDB 136
#define STAGE_W (128*LDA + 32*LDB)            // 8960 words per stage
#define GEMM_SMEM (3 * STAGE_W * 4)           // 107520 B
#define NCH (EMB / 32)                        // 32 K-chunks

// ---------------------------------------------------------------------------
// Kernel 1: QKV = X @ Wqkv via TF32 tensor cores + 3-stage cp.async pipeline,
// fused RoPE, scatter to [B,H,T,D].
// ---------------------------------------------------------------------------
__global__ __launch_bounds__(256, 2)
void qkv_rope_kernel(const float* __restrict__ X, const float* __restrict__ W,
                     const float* __restrict__ cp, const float* __restrict__ snp)
{
    extern __shared__ float smf[];

    const int tid  = threadIdx.x;
    const int lane = tid & 31;
    const int warp = tid >> 5;
    const int g = lane >> 2, c = lane & 3;
    const int m_base = (warp & 1) * 64;
    const int n_base = (warp >> 1) * 32;
    const int m0 = blockIdx.y * 128;
    const int n0 = blockIdx.x * 128;

    float acc[4][4][4];
#pragma unroll
    for (int i = 0; i < 4; i++)
#pragma unroll
        for (int j = 0; j < 4; j++)
#pragma unroll
            for (int r = 0; r < 4; r++) acc[i][j][r] = 0.f;

    // Per-thread load coordinates
    const int arow = tid >> 3, ac4 = (tid & 7) * 4;     // A: 128 rows x 32 cols (128 thr-groups via it)
    const int brow = tid >> 5, bc4 = (tid & 31) * 4;    // B: 32 rows x 128 cols

    auto issue = [&](int ch) {
        if (ch < NCH) {
            float* stA = smf + (ch % 3) * STAGE_W;
            float* stB = stA + 128 * LDA;
            int k0 = ch * 32;
#pragma unroll
            for (int it = 0; it < 4; it++) {
                int row = arow + it * 32;
                cp_async16(&stA[row * LDA + ac4],
                           &X[(size_t)(m0 + row) * EMB + k0 + ac4]);
            }
#pragma unroll
            for (int it = 0; it < 4; it++) {
                int row = brow + it * 8;
                cp_async16(&stB[row * LDB + bc4],
                           &W[(size_t)(k0 + row) * NQKV + n0 + bc4]);
            }
        }
        asm volatile("cp.async.commit_group;");
    };

    issue(0);
    issue(1);

    for (int ch = 0; ch < NCH; ch++) {
        asm volatile("cp.async.wait_group 1;");
        __syncthreads();
        issue(ch + 2);   // overwrites stage (ch-1)%3 — safe: all warps passed barrier

        const float* stA = smf + (ch % 3) * STAGE_W;
        const float* stB = stA + 128 * LDA;

#pragma unroll
        for (int ks = 0; ks < 4; ks++) {
            unsigned int a[4][4], b[4][2];
#pragma unroll
            for (int mf = 0; mf < 4; mf++) {
                const float* pa = &stA[(m_base + mf * 16 + g) * LDA + ks * 8];
                a[mf][0] = f2tf32(pa[c]);
                a[mf][1] = f2tf32(pa[8 * LDA + c]);
                a[mf][2] = f2tf32(pa[c + 4]);
                a[mf][3] = f2tf32(pa[8 * LDA + c + 4]);
            }
#pragma unroll
            for (int nf = 0; nf < 4; nf++) {
                const float* pb = &stB[(ks * 8 + c) * LDB + n_base + nf * 8 + g];
                b[nf][0] = f2tf32(pb[0]);
                b[nf][1] = f2tf32(pb[4 * LDB]);
            }
#pragma unroll
            for (int mf = 0; mf < 4; mf++)
#pragma unroll
                for (int nf = 0; nf < 4; nf++)
                    mma_tf32(acc[mf][nf], a[mf], b[nf]);
        }
    }

    // Epilogue: RoPE + scatter
#pragma unroll
    for (int mf = 0; mf < 4; mf++) {
#pragma unroll
        for (int half = 0; half < 2; half++) {
            int row = m0 + m_base + mf * 16 + g + half * 8;
            int b_ = row >> 11;
            int t_ = row & (SEQ - 1);
#pragma unroll
            for (int nf = 0; nf < 4; nf++) {
                int col = n0 + n_base + nf * 8 + c * 2;
                float v0 = acc[mf][nf][half * 2 + 0];
                float v1 = acc[mf][nf][half * 2 + 1];
                int seg = col >> 10;
                int jc  = col & 1023;
                int h = jc >> 6, d = jc & 63;
                float* dst = (seg == 0) ? g_q : (seg == 1) ? g_k : g_v;
                int idx = ((b_ * NH + h) * SEQ + t_) * HD + d;
                float2 o2;
                if (seg < 2) {
                    float cc = cp [t_ * (HD / 2) + (d >> 1)];
                    float ss = snp[t_ * (HD / 2) + (d >> 1)];
                    o2.x = v0 * cc - v1 * ss;
                    o2.y = v0 * ss + v1 * cc;
                } else {
                    o2.x = v0; o2.y = v1;
                }
                *(float2*)&dst[idx] = o2;
            }
        }
    }
}

// ---------------------------------------------------------------------------
// Kernel 2: causal flash attention, TF32 tensor cores.
// Block = 64 q-rows x one (b,h). 128 threads, 4 warps x 16 rows.
// (unchanged from the passing round-6 kernel)
// ---------------------------------------------------------------------------
#define LDQ 68
#define LDK 68
#define LDV 72
#define ATTN_SMEM ((64*LDQ + 64*LDK + 64*LDV) * 4)   // 53248 B

__global__ __launch_bounds__(128)
void attn_kernel()
{
    extern __shared__ unsigned int smu[];
    unsigned int* sq = smu;
    unsigned int* sk = sq + 64 * LDQ;
    unsigned int* sv = sk + 64 * LDK;

    const int qt = gridDim.x - 1 - blockIdx.x;
    const int bh = blockIdx.y;
    const float* Qb = g_q + (size_t)bh * SEQ * HD;
    const float* Kb = g_k + (size_t)bh * SEQ * HD;
    const float* Vb = g_v + (size_t)bh * SEQ * HD;

    const int tid  = threadIdx.x;
    const int lane = tid & 31;
    const int warp = tid >> 5;
    const int g = lane >> 2, c = lane & 3;
    const int rw = warp * 16;
    const float SCALE = 0.125f;

#pragma unroll
    for (int it = 0; it < 8; it++) {
        int idx = tid + it * 128;
        int row = idx >> 4, c4 = (idx & 15) * 4;
        float4 v = *(const float4*)&Qb[(size_t)(qt * 64 + row) * HD + c4];
        unsigned int* d = &sq[row * LDQ + c4];
        d[0] = f2tf32(v.x * SCALE); d[1] = f2tf32(v.y * SCALE);
        d[2] = f2tf32(v.z * SCALE); d[3] = f2tf32(v.w * SCALE);
    }
    __syncthreads();

    unsigned int qf[8][4];
#pragma unroll
    for (int kf = 0; kf < 8; kf++) {
        const unsigned int* p = &sq[(rw + g) * LDQ + kf * 8];
        qf[kf][0] = p[c];
        qf[kf][1] = p[8 * LDQ + c];
        qf[kf][2] = p[c + 4];
        qf[kf][3] = p[8 * LDQ + c + 4];
    }
    __syncthreads();

    float oacc[8][4];
#pragma unroll
    for (int df = 0; df < 8; df++)
#pragma unroll
        for (int r = 0; r < 4; r++) oacc[df][r] = 0.f;
    float mi0 = -1e30f, mi1 = -1e30f, li0 = 0.f, li1 = 0.f;

    for (int kt = 0; kt <= qt; kt++) {
#pragma unroll
        for (int it = 0; it < 8; it++) {
            int idx = tid + it * 128;
            int row = idx >> 4, c4 = (idx & 15) * 4;
            float4 kv = *(const float4*)&Kb[(size_t)(kt * 64 + row) * HD + c4];
            float4 vv = *(const float4*)&Vb[(size_t)(kt * 64 + row) * HD + c4];
            unsigned int* dk = &sk[row * LDK + c4];
            dk[0] = f2tf32(kv.x); dk[1] = f2tf32(kv.y);
            dk[2] = f2tf32(kv.z); dk[3] = f2tf32(kv.w);
            unsigned int* dv = &sv[row * LDV + c4];
            dv[0] = f2tf32(vv.x); dv[1] = f2tf32(vv.y);
            dv[2] = f2tf32(vv.z); dv[3] = f2tf32(vv.w);
        }
        __syncthreads();

        float sacc[8][4];
#pragma unroll
        for (int nf = 0; nf < 8; nf++)
#pragma unroll
            for (int r = 0; r < 4; r++) sacc[nf][r] = 0.f;

#pragma unroll
        for (int nf = 0; nf < 8; nf++) {
#pragma unroll
            for (int kf = 0; kf < 8; kf++) {
                unsigned int b[2];
                const unsigned int* pb = &sk[(nf * 8 + g) * LDK + kf * 8];
                b[0] = pb[c];
                b[1] = pb[c + 4];
                mma_tf32(sacc[nf], qf[kf], b);
            }
        }

        if (kt == qt) {
            int r0 = rw + g, r1 = rw + g + 8;
#pragma unroll
            for (int nf = 0; nf < 8; nf++) {
                int col0 = nf * 8 + 2 * c, col1 = col0 + 1;
                if (col0 > r0) sacc[nf][0] = -1e30f;
                if (col1 > r0) sacc[nf][1] = -1e30f;
                if (col0 > r1) sacc[nf][2] = -1e30f;
                if (col1 > r1) sacc[nf][3] = -1e30f;
            }
        }

        float m0 = -1e30f, m1 = -1e30f;
#pragma unroll
        for (int nf = 0; nf < 8; nf++) {
            m0 = fmaxf(m0, fmaxf(sacc[nf][0], sacc[nf][1]));
            m1 = fmaxf(m1, fmaxf(sacc[nf][2], sacc[nf][3]));
        }
        m0 = fmaxf(m0, __shfl_xor_sync(0xffffffffu, m0, 1));
        m0 = fmaxf(m0, __shfl_xor_sync(0xffffffffu, m0, 2));
        m1 = fmaxf(m1, __shfl_xor_sync(0xffffffffu, m1, 1));
        m1 = fmaxf(m1, __shfl_xor_sync(0xffffffffu, m1, 2));
        float mn0 = fmaxf(mi0, m0), mn1 = fmaxf(mi1, m1);
        float al0 = __expf(mi0 - mn0), al1 = __expf(mi1 - mn1);
        mi0 = mn0; mi1 = mn1;

        float rs0 = 0.f, rs1 = 0.f;
#pragma unroll
        for (int nf = 0; nf < 8; nf++) {
            sacc[nf][0] = __expf(sacc[nf][0] - mn0);
            sacc[nf][1] = __expf(sacc[nf][1] - mn0);
            sacc[nf][2] = __expf(sacc[nf][2] - mn1);
            sacc[nf][3] = __expf(sacc[nf][3] - mn1);
            rs0 += sacc[nf][0] + sacc[nf][1];
            rs1 += sacc[nf][2] + sacc[nf][3];
        }
        rs0 += __shfl_xor_sync(0xffffffffu, rs0, 1);
        rs0 += __shfl_xor_sync(0xffffffffu, rs0, 2);
        rs1 += __shfl_xor_sync(0xffffffffu, rs1, 1);
        rs1 += __shfl_xor_sync(0xffffffffu, rs1, 2);
        li0 = li0 * al0 + rs0;
        li1 = li1 * al1 + rs1;
#pragma unroll
        for (int df = 0; df < 8; df++) {
            oacc[df][0] *= al0; oacc[df][1] *= al0;
            oacc[df][2] *= al1; oacc[df][3] *= al1;
        }

#pragma unroll
        for (int nf = 0; nf < 8; nf++) {
            sq[(rw + g)     * LDQ + nf * 8 + 2 * c]     = f2tf32(sacc[nf][0]);
            sq[(rw + g)     * LDQ + nf * 8 + 2 * c + 1] = f2tf32(sacc[nf][1]);
            sq[(rw + g + 8) * LDQ + nf * 8 + 2 * c]     = f2tf32(sacc[nf][2]);
            sq[(rw + g + 8) * LDQ + nf * 8 + 2 * c + 1] = f2tf32(sacc[nf][3]);
        }
        __syncwarp();

#pragma unroll
        for (int jf = 0; jf < 8; jf++) {
            unsigned int pa[4];
            const unsigned int* pp = &sq[(rw + g) * LDQ + jf * 8];
            pa[0] = pp[c];
            pa[1] = pp[8 * LDQ + c];
            pa[2] = pp[c + 4];
            pa[3] = pp[8 * LDQ + c + 4];
#pragma unroll
            for (int df = 0; df < 8; df++) {
                unsigned int b[2];
                const unsigned int* pv = &sv[(jf * 8 + c) * LDV + df * 8 + g];
                b[0] = pv[0];
                b[1] = pv[4 * LDV];
                mma_tf32(oacc[df], pa, b);
            }
        }
        __syncthreads();
    }

    const int b_ = bh >> 4, h = bh & 15;
    const float inv0 = 1.f / li0, inv1 = 1.f / li1;
    const int t0 = qt * 64 + rw + g, t1 = t0 + 8;
#pragma unroll
    for (int df = 0; df < 8; df++) {
        int col = h * HD + df * 8 + 2 * c;
        float2 o0, o1;
        o0.x = oacc[df][0] * inv0; o0.y = oacc[df][1] * inv0;
        o1.x = oacc[df][2] * inv1; o1.y = oacc[df][3] * inv1;
        *(float2*)&g_attn[(size_t)(b_ * SEQ + t0) * EMB + col] = o0;
        *(float2*)&g_attn[(size_t)(b_ * SEQ + t1) * EMB + col] = o1;
    }
}

// ---------------------------------------------------------------------------
// Kernel 3: out = attn @ Wproj + bproj, TF32 + 3-stage cp.async pipeline
// ---------------------------------------------------------------------------
__global__ __launch_bounds__(256, 2)
void proj_kernel(const float* __restrict__ W, const float* __restrict__ bias,
                 float* __restrict__ out)
{
    extern __shared__ float smf[];

    const int tid  = threadIdx.x;
    const int lane = tid & 31;
    const int warp = tid >> 5;
    const int g = lane >> 2, c = lane & 3;
    const int m_base = (warp & 1) * 64;
    const int n_base = (warp >> 1) * 32;
    const int m0 = blockIdx.y * 128;
    const int n0 = blockIdx.x * 128;

    float acc[4][4][4];
#pragma unroll
    for (int i = 0; i < 4; i++)
#pragma unroll
        for (int j = 0; j < 4; j++)
#pragma unroll
            for (int r = 0; r < 4; r++) acc[i][j][r] = 0.f;

    const int arow = tid >> 3, ac4 = (tid & 7) * 4;
    const int brow = tid >> 5, bc4 = (tid & 31) * 4;

    auto issue = [&](int ch) {
        if (ch < NCH) {
            float* stA = smf + (ch % 3) * STAGE_W;
            float* stB = stA + 128 * LDA;
            int k0 = ch * 32;
#pragma unroll
            for (int it = 0; it < 4; it++) {
                int row = arow + it * 32;
                cp_async16(&stA[row * LDA + ac4],
                           &g_attn[(size_t)(m0 + row) * EMB + k0 + ac4]);
            }
#pragma unroll
            for (int it = 0; it < 4; it++) {
                int row = brow + it * 8;
                cp_async16(&stB[row * LDB + bc4],
                           &W[(size_t)(k0 + row) * EMB + n0 + bc4]);
            }
        }
        asm volatile("cp.async.commit_group;");
    };

    issue(0);
    issue(1);

    for (int ch = 0; ch < NCH; ch++) {
        asm volatile("cp.async.wait_group 1;");
        __syncthreads();
        issue(ch + 2);

        const float* stA = smf + (ch % 3) * STAGE_W;
        const float* stB = stA + 128 * LDA;

#pragma unroll
        for (int ks = 0; ks < 4; ks++) {
            unsigned int a[4][4], b[4][2];
#pragma unroll
            for (int mf = 0; mf < 4; mf++) {
                const float* pa = &stA[(m_base + mf * 16 + g) * LDA + ks * 8];
                a[mf][0] = f2tf32(pa[c]);
                a[mf][1] = f2tf32(pa[8 * LDA + c]);
                a[mf][2] = f2tf32(pa[c + 4]);
                a[mf][3] = f2tf32(pa[8 * LDA + c + 4]);
            }
#pragma unroll
            for (int nf = 0; nf < 4; nf++) {
                const float* pb = &stB[(ks * 8 + c) * LDB + n_base + nf * 8 + g];
                b[nf][0] = f2tf32(pb[0]);
                b[nf][1] = f2tf32(pb[4 * LDB]);
            }
#pragma unroll
            for (int mf = 0; mf < 4; mf++)
#pragma unroll
                for (int nf = 0; nf < 4; nf++)
                    mma_tf32(acc[mf][nf], a[mf], b[nf]);
        }
    }

#pragma unroll
    for (int mf = 0; mf < 4; mf++) {
#pragma unroll
        for (int half = 0; half < 2; half++) {
            int row = m0 + m_base + mf * 16 + g + half * 8;
#pragma unroll
            for (int nf = 0; nf < 4; nf++) {
                int col = n0 + n_base + nf * 8 + c * 2;
                float2 o2;
                o2.x = acc[mf][nf][half * 2 + 0] + bias[col + 0];
                o2.y = acc[mf][nf][half * 2 + 1] + bias[col + 1];
                *(float2*)&out[(size_t)row * EMB + col] = o2;
            }
        }
    }
}

// ---------------------------------------------------------------------------
extern "C" void kernel_launch(void* const* d_in, const int* in_sizes, int n_in,
                              void* d_out, int out_size)
{
    const float* x     = (const float*)d_in[0];
    const float* Wqkv  = (const float*)d_in[1];
    const float* Wproj = (const float*)d_in[2];
    const float* bproj = (const float*)d_in[3];
    const float* cosp  = (const float*)d_in[4];
    const float* sinp  = (const float*)d_in[5];
    float* out = (float*)d_out;

    cudaFuncSetAttribute(qkv_rope_kernel,
                         cudaFuncAttributeMaxDynamicSharedMemorySize, GEMM_SMEM);
    cudaFuncSetAttribute(attn_kernel,
                         cudaFuncAttributeMaxDynamicSharedMemorySize, ATTN_SMEM);
    cudaFuncSetAttribute(proj_kernel,
                         cudaFuncAttributeMaxDynamicSharedMemorySize, GEMM_SMEM);

    qkv_rope_kernel<<<dim3(NQKV / 128, MTOT / 128), 256, GEMM_SMEM>>>(x, Wqkv, cosp, sinp);
    attn_kernel<<<dim3(SEQ / 64, BATCH * NH), 128, ATTN_SMEM>>>();
    proj_kernel<<<dim3(EMB / 128, MTOT / 128), 256, GEMM_SMEM>>>(Wproj, bproj, out);
}

// round 9
// speedup vs baseline: 3.8932x; 1.1194x over previous
#include <cuda_runtime.h>

#define EMB   1024
#define NH    16
#define HD    64
#define SEQ   2048
#define BATCH 2
#define MTOT  (BATCH*SEQ)      // 4096
#define NQKV  (3*EMB)          // 3072

// Scratch (device globals: no allocation allowed in kernel_launch)
__device__ float g_q[BATCH*NH*SEQ*HD];
__device__ float g_k[BATCH*NH*SEQ*HD];
__device__ float g_v[BATCH*NH*SEQ*HD];
__device__ float g_attn[MTOT*EMB];
// Pre-converted (tf32-rounded, fp32 bit container) copies
__device__ float g_x[MTOT*EMB];
__device__ float g_wqkv[EMB*NQKV];
__device__ float g_wproj[EMB*EMB];

// ---------------------------------------------------------------------------
// TF32 helpers
// ---------------------------------------------------------------------------
__device__ __forceinline__ unsigned int f2tf32(float f) {
    unsigned int u;
    asm("cvt.rna.tf32.f32 %0, %1;" : "=r"(u) : "f"(f));
    return u;
}

__device__ __forceinline__ void mma_tf32(float c[4],
                                         const unsigned int a[4],
                                         const unsigned int b[2]) {
    asm volatile(
        "mma.sync.aligned.m16n8k8.row.col.f32.tf32.tf32.f32 "
        "{%0,%1,%2,%3}, {%4,%5,%6,%7}, {%8,%9}, {%0,%1,%2,%3};"
        : "+f"(c[0]), "+f"(c[1]), "+f"(c[2]), "+f"(c[3])
        : "r"(a[0]), "r"(a[1]), "r"(a[2]), "r"(a[3]),
          "r"(b[0]), "r"(b[1]));
}

__device__ __forceinline__ void cp_async16(void* smem_dst, const void* gsrc) {
    unsigned int d = (unsigned int)__cvta_generic_to_shared(smem_dst);
    asm volatile("cp.async.cg.shared.global [%0], [%1], 16;" :: "r"(d), "l"(gsrc));
}

// ldmatrix x4: four 8x8 b16 tiles == four 8x4 tf32 tiles (reg i <- matrix i;
// within a matrix lane L gets row L>>2, tf32 elem L&3 — the mma frag mapping).
__device__ __forceinline__ void ldsm4(unsigned int r[4], const void* p) {
    unsigned int a = (unsigned int)__cvta_generic_to_shared(p);
    asm volatile("ldmatrix.sync.aligned.m8n8.x4.shared.b16 {%0,%1,%2,%3}, [%4];"
        : "=r"(r[0]), "=r"(r[1]), "=r"(r[2]), "=r"(r[3]) : "r"(a));
}

// ---------------------------------------------------------------------------
// Kernel 0: pre-convert X, Wqkv, Wproj to tf32 bits (one pass, memory-bound)
// ---------------------------------------------------------------------------
#define NX4 (MTOT*EMB/4)
#define NW4 (EMB*NQKV/4)
#define NP4 (EMB*EMB/4)

__global__ __launch_bounds__(256)
void cvt_kernel(const float* __restrict__ x, const float* __restrict__ wqkv,
                const float* __restrict__ wproj)
{
    int i = blockIdx.x * 256 + threadIdx.x;
    const float4* src; float4* dst; int j;
    if (i < NX4)            { src = (const float4*)x;     dst = (float4*)g_x;     j = i; }
    else if (i < NX4+NW4)   { src = (const float4*)wqkv;  dst = (float4*)g_wqkv;  j = i - NX4; }
    else if (i < NX4+NW4+NP4){ src = (const float4*)wproj; dst = (float4*)g_wproj; j = i - NX4 - NW4; }
    else return;
    float4 v = src[j];
    float4 o;
    o.x = __uint_as_float(f2tf32(v.x));
    o.y = __uint_as_float(f2tf32(v.y));
    o.z = __uint_as_float(f2tf32(v.z));
    o.w = __uint_as_float(f2tf32(v.w));
    dst[j] = o;
}

// GEMM tile strides (words): A stride 36 (=4 mod 32), B stride 136 (=8 mod 32)
#define LDA 36
#define LDB 136
#define STAGE_W (128*LDA + 32*LDB)            // 8960 words per stage
#define GEMM_SMEM (3 * STAGE_W * 4)           // 107520 B
#define NCH (EMB / 32)                        // 32 K-chunks

// ---------------------------------------------------------------------------
// Kernel 1: QKV = X @ Wqkv, TF32 mma + cp.async 3-stage + ldmatrix A-frags.
// Fused RoPE; writes q (scaled), k, v tf32-rounded to [B,H,T,D].
// ---------------------------------------------------------------------------
__global__ __launch_bounds__(256, 2)
void qkv_rope_kernel(const float* __restrict__ cp, const float* __restrict__ snp)
{
    extern __shared__ float smf[];

    const int tid  = threadIdx.x;
    const int lane = tid & 31;
    const int warp = tid >> 5;
    const int g = lane >> 2, c = lane & 3;
    const int m_base = (warp & 1) * 64;
    const int n_base = (warp >> 1) * 32;
    const int m0 = blockIdx.y * 128;
    const int n0 = blockIdx.x * 128;

    // ldmatrix A-style per-lane offsets (16x8 tile, 4 matrices)
    const int rA = ((lane >> 3) & 1) * 8 + (lane & 7);
    const int cA = (lane >> 4) * 4;

    float acc[4][4][4];
#pragma unroll
    for (int i = 0; i < 4; i++)
#pragma unroll
        for (int j = 0; j < 4; j++)
#pragma unroll
            for (int r = 0; r < 4; r++) acc[i][j][r] = 0.f;

    const int arow = tid >> 3, ac4 = (tid & 7) * 4;
    const int brow = tid >> 5, bc4 = (tid & 31) * 4;

    auto issue = [&](int ch) {
        if (ch < NCH) {
            float* stA = smf + (ch % 3) * STAGE_W;
            float* stB = stA + 128 * LDA;
            int k0 = ch * 32;
#pragma unroll
            for (int it = 0; it < 4; it++) {
                int row = arow + it * 32;
                cp_async16(&stA[row * LDA + ac4],
                           &g_x[(size_t)(m0 + row) * EMB + k0 + ac4]);
            }
#pragma unroll
            for (int it = 0; it < 4; it++) {
                int row = brow + it * 8;
                cp_async16(&stB[row * LDB + bc4],
                           &g_wqkv[(size_t)(k0 + row) * NQKV + n0 + bc4]);
            }
        }
        asm volatile("cp.async.commit_group;");
    };

    issue(0);
    issue(1);

    for (int ch = 0; ch < NCH; ch++) {
        asm volatile("cp.async.wait_group 1;");
        __syncthreads();
        issue(ch + 2);

        const float* stA = smf + (ch % 3) * STAGE_W;
        const float* stB = stA + 128 * LDA;

#pragma unroll
        for (int ks = 0; ks < 4; ks++) {
            unsigned int a[4][4], b[4][2];
#pragma unroll
            for (int mf = 0; mf < 4; mf++)
                ldsm4(a[mf], &stA[(m_base + mf * 16 + rA) * LDA + ks * 8 + cA]);
#pragma unroll
            for (int nf = 0; nf < 4; nf++) {
                const float* pb = &stB[(ks * 8 + c) * LDB + n_base + nf * 8 + g];
                b[nf][0] = __float_as_uint(pb[0]);
                b[nf][1] = __float_as_uint(pb[4 * LDB]);
            }
#pragma unroll
            for (int mf = 0; mf < 4; mf++)
#pragma unroll
                for (int nf = 0; nf < 4; nf++)
                    mma_tf32(acc[mf][nf], a[mf], b[nf]);
        }
    }

    // Epilogue: RoPE + tf32-round + scatter (q pre-scaled by 1/8)
#pragma unroll
    for (int mf = 0; mf < 4; mf++) {
#pragma unroll
        for (int half = 0; half < 2; half++) {
            int row = m0 + m_base + mf * 16 + g + half * 8;
            int b_ = row >> 11;
            int t_ = row & (SEQ - 1);
#pragma unroll
            for (int nf = 0; nf < 4; nf++) {
                int col = n0 + n_base + nf * 8 + c * 2;
                float v0 = acc[mf][nf][half * 2 + 0];
                float v1 = acc[mf][nf][half * 2 + 1];
                int seg = col >> 10;
                int jc  = col & 1023;
                int h = jc >> 6, d = jc & 63;
                float* dst = (seg == 0) ? g_q : (seg == 1) ? g_k : g_v;
                int idx = ((b_ * NH + h) * SEQ + t_) * HD + d;
                float rx, ry;
                if (seg < 2) {
                    float cc = cp [t_ * (HD / 2) + (d >> 1)];
                    float ss = snp[t_ * (HD / 2) + (d >> 1)];
                    rx = v0 * cc - v1 * ss;
                    ry = v0 * ss + v1 * cc;
                    if (seg == 0) { rx *= 0.125f; ry *= 0.125f; }
                } else {
                    rx = v0; ry = v1;
                }
                float2 o2;
                o2.x = __uint_as_float(f2tf32(rx));
                o2.y = __uint_as_float(f2tf32(ry));
                *(float2*)&dst[idx] = o2;
            }
        }
    }
}

// ---------------------------------------------------------------------------
// Kernel 2: causal flash attention, TF32 mma, cp.async double-buffered K/V,
// ldmatrix for Q/K/P fragments. Inputs pre-rounded by qkv epilogue.
// ---------------------------------------------------------------------------
#define LDQ 68
#define LDK 68
#define LDV 72
#define KV_W (64*LDK + 64*LDV)                       // 8960 words per buffer
#define ATTN_SMEM ((64*LDQ + 2*KV_W) * 4)            // 89088 B

__global__ __launch_bounds__(128)
void attn_kernel()
{
    extern __shared__ float smf[];
    float* sq = smf;                                  // Q, then P (aliased)

    const int qt = gridDim.x - 1 - blockIdx.x;        // big tiles first
    const int bh = blockIdx.y;
    const float* Qb = g_q + (size_t)bh * SEQ * HD;
    const float* Kb = g_k + (size_t)bh * SEQ * HD;
    const float* Vb = g_v + (size_t)bh * SEQ * HD;

    const int tid  = threadIdx.x;
    const int lane = tid & 31;
    const int warp = tid >> 5;
    const int g = lane >> 2, c = lane & 3;
    const int rw = warp * 16;
    // ldmatrix per-lane offsets
    const int rA = ((lane >> 3) & 1) * 8 + (lane & 7);  // A-style (16x8)
    const int cA = (lane >> 4) * 4;
    const int rB = ((lane >> 4) & 1) * 8 + (lane & 7);  // B-style ([n][k], 2 n-grps)
    const int cB = ((lane >> 3) & 1) * 4;

    auto skb = [&](int b) { return smf + 64 * LDQ + b * KV_W; };
    auto svb = [&](int b) { return smf + 64 * LDQ + b * KV_W + 64 * LDK; };

    auto issue_kv = [&](int kt, int b) {
        if (kt <= qt) {
            float* dk = skb(b);
            float* dv = svb(b);
#pragma unroll
            for (int it = 0; it < 8; it++) {
                int idx = tid + it * 128;
                int row = idx >> 4, c4 = (idx & 15) * 4;
                cp_async16(&dk[row * LDK + c4], &Kb[(size_t)(kt * 64 + row) * HD + c4]);
                cp_async16(&dv[row * LDV + c4], &Vb[(size_t)(kt * 64 + row) * HD + c4]);
            }
        }
        asm volatile("cp.async.commit_group;");
    };

    // Preamble: Q + first K/V tile, one group
#pragma unroll
    for (int it = 0; it < 8; it++) {
        int idx = tid + it * 128;
        int row = idx >> 4, c4 = (idx & 15) * 4;
        cp_async16(&sq[row * LDQ + c4], &Qb[(size_t)(qt * 64 + row) * HD + c4]);
    }
    issue_kv(0, 0);

    unsigned int qf[8][4];
    float oacc[8][4];
#pragma unroll
    for (int df = 0; df < 8; df++)
#pragma unroll
        for (int r = 0; r < 4; r++) oacc[df][r] = 0.f;
    float mi0 = -1e30f, mi1 = -1e30f, li0 = 0.f, li1 = 0.f;

    for (int kt = 0; kt <= qt; kt++) {
        asm volatile("cp.async.wait_group 0;");
        __syncthreads();
        if (kt == 0) {
#pragma unroll
            for (int kf = 0; kf < 8; kf++)
                ldsm4(qf[kf], &sq[(rw + rA) * LDQ + kf * 8 + cA]);
            __syncthreads();   // sq now reusable as P buffer
        }
        issue_kv(kt + 1, (kt + 1) & 1);

        const float* sk = skb(kt & 1);
        const float* sv = svb(kt & 1);

        // S = Q K^T
        float sacc[8][4];
#pragma unroll
        for (int nf = 0; nf < 8; nf++)
#pragma unroll
            for (int r = 0; r < 4; r++) sacc[nf][r] = 0.f;

#pragma unroll
        for (int kf = 0; kf < 8; kf++) {
            unsigned int bF[4][4];
#pragma unroll
            for (int p = 0; p < 4; p++)
                ldsm4(bF[p], &sk[(p * 16 + rB) * LDK + kf * 8 + cB]);
#pragma unroll
            for (int nf = 0; nf < 8; nf++) {
                unsigned int b2[2] = { bF[nf >> 1][(nf & 1) * 2],
                                       bF[nf >> 1][(nf & 1) * 2 + 1] };
                mma_tf32(sacc[nf], qf[kf], b2);
            }
        }

        // Causal mask on diagonal tile
        if (kt == qt) {
            int r0 = rw + g, r1 = rw + g + 8;
#pragma unroll
            for (int nf = 0; nf < 8; nf++) {
                int col0 = nf * 8 + 2 * c, col1 = col0 + 1;
                if (col0 > r0) sacc[nf][0] = -1e30f;
                if (col1 > r0) sacc[nf][1] = -1e30f;
                if (col0 > r1) sacc[nf][2] = -1e30f;
                if (col1 > r1) sacc[nf][3] = -1e30f;
            }
        }

        // Online softmax
        float m0 = -1e30f, m1 = -1e30f;
#pragma unroll
        for (int nf = 0; nf < 8; nf++) {
            m0 = fmaxf(m0, fmaxf(sacc[nf][0], sacc[nf][1]));
            m1 = fmaxf(m1, fmaxf(sacc[nf][2], sacc[nf][3]));
        }
        m0 = fmaxf(m0, __shfl_xor_sync(0xffffffffu, m0, 1));
        m0 = fmaxf(m0, __shfl_xor_sync(0xffffffffu, m0, 2));
        m1 = fmaxf(m1, __shfl_xor_sync(0xffffffffu, m1, 1));
        m1 = fmaxf(m1, __shfl_xor_sync(0xffffffffu, m1, 2));
        float mn0 = fmaxf(mi0, m0), mn1 = fmaxf(mi1, m1);
        float al0 = __expf(mi0 - mn0), al1 = __expf(mi1 - mn1);
        mi0 = mn0; mi1 = mn1;

        float rs0 = 0.f, rs1 = 0.f;
#pragma unroll
        for (int nf = 0; nf < 8; nf++) {
            sacc[nf][0] = __expf(sacc[nf][0] - mn0);
            sacc[nf][1] = __expf(sacc[nf][1] - mn0);
            sacc[nf][2] = __expf(sacc[nf][2] - mn1);
            sacc[nf][3] = __expf(sacc[nf][3] - mn1);
            rs0 += sacc[nf][0] + sacc[nf][1];
            rs1 += sacc[nf][2] + sacc[nf][3];
        }
        rs0 += __shfl_xor_sync(0xffffffffu, rs0, 1);
        rs0 += __shfl_xor_sync(0xffffffffu, rs0, 2);
        rs1 += __shfl_xor_sync(0xffffffffu, rs1, 1);
        rs1 += __shfl_xor_sync(0xffffffffu, rs1, 2);
        li0 = li0 * al0 + rs0;
        li1 = li1 * al1 + rs1;
#pragma unroll
        for (int df = 0; df < 8; df++) {
            oacc[df][0] *= al0; oacc[df][1] *= al0;
            oacc[df][2] *= al1; oacc[df][3] *= al1;
        }

        // P -> smem (tf32), per-warp rows rw..rw+15
#pragma unroll
        for (int nf = 0; nf < 8; nf++) {
            sq[(rw + g)     * LDQ + nf * 8 + 2 * c]     = __uint_as_float(f2tf32(sacc[nf][0]));
            sq[(rw + g)     * LDQ + nf * 8 + 2 * c + 1] = __uint_as_float(f2tf32(sacc[nf][1]));
            sq[(rw + g + 8) * LDQ + nf * 8 + 2 * c]     = __uint_as_float(f2tf32(sacc[nf][2]));
            sq[(rw + g + 8) * LDQ + nf * 8 + 2 * c + 1] = __uint_as_float(f2tf32(sacc[nf][3]));
        }
        __syncwarp();

        // O += P V
#pragma unroll
        for (int jf = 0; jf < 8; jf++) {
            unsigned int pa[4];
            ldsm4(pa, &sq[(rw + rA) * LDQ + jf * 8 + cA]);
#pragma unroll
            for (int df = 0; df < 8; df++) {
                unsigned int b2[2];
                const float* pv = &sv[(jf * 8 + c) * LDV + df * 8 + g];
                b2[0] = __float_as_uint(pv[0]);
                b2[1] = __float_as_uint(pv[4 * LDV]);
                mma_tf32(oacc[df], pa, b2);
            }
        }
    }

    // Epilogue: normalize, tf32-round, write [B,T,C]
    const int b_ = bh >> 4, h = bh & 15;
    const float inv0 = 1.f / li0, inv1 = 1.f / li1;
    const int t0 = qt * 64 + rw + g, t1 = t0 + 8;
#pragma unroll
    for (int df = 0; df < 8; df++) {
        int col = h * HD + df * 8 + 2 * c;
        float2 o0, o1;
        o0.x = __uint_as_float(f2tf32(oacc[df][0] * inv0));
        o0.y = __uint_as_float(f2tf32(oacc[df][1] * inv0));
        o1.x = __uint_as_float(f2tf32(oacc[df][2] * inv1));
        o1.y = __uint_as_float(f2tf32(oacc[df][3] * inv1));
        *(float2*)&g_attn[(size_t)(b_ * SEQ + t0) * EMB + col] = o0;
        *(float2*)&g_attn[(size_t)(b_ * SEQ + t1) * EMB + col] = o1;
    }
}

// ---------------------------------------------------------------------------
// Kernel 3: out = attn @ Wproj + bproj (inputs pre-rounded; no cvt in loop)
// ---------------------------------------------------------------------------
__global__ __launch_bounds__(256, 2)
void proj_kernel(const float* __restrict__ bias, float* __restrict__ out)
{
    extern __shared__ float smf[];

    const int tid  = threadIdx.x;
    const int lane = tid & 31;
    const int warp = tid >> 5;
    const int g = lane >> 2, c = lane & 3;
    const int m_base = (warp & 1) * 64;
    const int n_base = (warp >> 1) * 32;
    const int m0 = blockIdx.y * 128;
    const int n0 = blockIdx.x * 128;

    const int rA = ((lane >> 3) & 1) * 8 + (lane & 7);
    const int cA = (lane >> 4) * 4;

    float acc[4][4][4];
#pragma unroll
    for (int i = 0; i < 4; i++)
#pragma unroll
        for (int j = 0; j < 4; j++)
#pragma unroll
            for (int r = 0; r < 4; r++) acc[i][j][r] = 0.f;

    const int arow = tid >> 3, ac4 = (tid & 7) * 4;
    const int brow = tid >> 5, bc4 = (tid & 31) * 4;

    auto issue = [&](int ch) {
        if (ch < NCH) {
            float* stA = smf + (ch % 3) * STAGE_W;
            float* stB = stA + 128 * LDA;
            int k0 = ch * 32;
#pragma unroll
            for (int it = 0; it < 4; it++) {
                int row = arow + it * 32;
                cp_async16(&stA[row * LDA + ac4],
                           &g_attn[(size_t)(m0 + row) * EMB + k0 + ac4]);
            }
#pragma unroll
            for (int it = 0; it < 4; it++) {
                int row = brow + it * 8;
                cp_async16(&stB[row * LDB + bc4],
                           &g_wproj[(size_t)(k0 + row) * EMB + n0 + bc4]);
            }
        }
        asm volatile("cp.async.commit_group;");
    };

    issue(0);
    issue(1);

    for (int ch = 0; ch < NCH; ch++) {
        asm volatile("cp.async.wait_group 1;");
        __syncthreads();
        issue(ch + 2);

        const float* stA = smf + (ch % 3) * STAGE_W;
        const float* stB = stA + 128 * LDA;

#pragma unroll
        for (int ks = 0; ks < 4; ks++) {
            unsigned int a[4][4], b[4][2];
#pragma unroll
            for (int mf = 0; mf < 4; mf++)
                ldsm4(a[mf], &stA[(m_base + mf * 16 + rA) * LDA + ks * 8 + cA]);
#pragma unroll
            for (int nf = 0; nf < 4; nf++) {
                const float* pb = &stB[(ks * 8 + c) * LDB + n_base + nf * 8 + g];
                b[nf][0] = __float_as_uint(pb[0]);
                b[nf][1] = __float_as_uint(pb[4 * LDB]);
            }
#pragma unroll
            for (int mf = 0; mf < 4; mf++)
#pragma unroll
                for (int nf = 0; nf < 4; nf++)
                    mma_tf32(acc[mf][nf], a[mf], b[nf]);
        }
    }

#pragma unroll
    for (int mf = 0; mf < 4; mf++) {
#pragma unroll
        for (int half = 0; half < 2; half++) {
            int row = m0 + m_base + mf * 16 + g + half * 8;
#pragma unroll
            for (int nf = 0; nf < 4; nf++) {
                int col = n0 + n_base + nf * 8 + c * 2;
                float2 o2;
                o2.x = acc[mf][nf][half * 2 + 0] + bias[col + 0];
                o2.y = acc[mf][nf][half * 2 + 1] + bias[col + 1];
                *(float2*)&out[(size_t)row * EMB + col] = o2;
            }
        }
    }
}

// ---------------------------------------------------------------------------
extern "C" void kernel_launch(void* const* d_in, const int* in_sizes, int n_in,
                              void* d_out, int out_size)
{
    const float* x     = (const float*)d_in[0];
    const float* Wqkv  = (const float*)d_in[1];
    const float* Wproj = (const float*)d_in[2];
    const float* bproj = (const float*)d_in[3];
    const float* cosp  = (const float*)d_in[4];
    const float* sinp  = (const float*)d_in[5];
    float* out = (float*)d_out;

    cudaFuncSetAttribute(qkv_rope_kernel,
                         cudaFuncAttributeMaxDynamicSharedMemorySize, GEMM_SMEM);
    cudaFuncSetAttribute(attn_kernel,
                         cudaFuncAttributeMaxDynamicSharedMemorySize, ATTN_SMEM);
    cudaFuncSetAttribute(proj_kernel,
                         cudaFuncAttributeMaxDynamicSharedMemorySize, GEMM_SMEM);

    cvt_kernel<<<(NX4 + NW4 + NP4 + 255) / 256, 256>>>(x, Wqkv, Wproj);
    qkv_rope_kernel<<<dim3(NQKV / 128, MTOT / 128), 256, GEMM_SMEM>>>(cosp, sinp);
    attn_kernel<<<dim3(SEQ / 64, BATCH * NH), 128, ATTN_SMEM>>>();
    proj_kernel<<<dim3(EMB / 128, MTOT / 128), 256, GEMM_SMEM>>>(bproj, out);
}